// round 1
// baseline (speedup 1.0000x reference)
#include <cuda_runtime.h>
#include <math.h>

#define BB 4
#define TT 2048
#define CC 1024
#define HH 16
#define DD 64
#define MROWS (BB*TT)     // 8192
#define NQKV  (3*CC)      // 3072

// Scratch (device globals — allocation-free per harness rules)
__device__ float g_q[BB*HH*TT*DD];   // (b,h,t,d), pre-scaled by 1/sqrt(D)
__device__ float g_k[BB*HH*TT*DD];
__device__ float g_v[BB*HH*TT*DD];
__device__ float g_o[MROWS*CC];      // (b*T+t, h*D+d)

// ---------------------------------------------------------------------------
// QKV GEMM: Y = x @ w_qkv + b_qkv ; scatter into g_q/g_k/g_v
// 128x128 block tile, K-tile 8, 256 threads, 8x8 microtile
// ---------------------------------------------------------------------------
__global__ __launch_bounds__(256) void qkv_gemm(
    const float* __restrict__ x, const float* __restrict__ w,
    const float* __restrict__ bias)
{
    __shared__ float As[8][128];
    __shared__ float Bs[8][128];
    const int tid = threadIdx.x;
    const int m0 = blockIdx.y * 128;
    const int n0 = blockIdx.x * 128;
    const int tm = (tid >> 4) * 8;
    const int tn = (tid & 15) * 8;

    const int arow = tid >> 1, acol = (tid & 1) * 4;   // A: 128x8 (float4)
    const int brow = tid >> 5, bcol = (tid & 31) * 4;  // B: 8x128 (float4)

    float acc[8][8];
    #pragma unroll
    for (int i = 0; i < 8; i++)
        #pragma unroll
        for (int j = 0; j < 8; j++) acc[i][j] = 0.f;

    for (int k0 = 0; k0 < CC; k0 += 8) {
        float4 a = *(const float4*)(x + (size_t)(m0 + arow) * CC + k0 + acol);
        As[acol + 0][arow] = a.x;
        As[acol + 1][arow] = a.y;
        As[acol + 2][arow] = a.z;
        As[acol + 3][arow] = a.w;
        float4 b = *(const float4*)(w + (size_t)(k0 + brow) * NQKV + n0 + bcol);
        *(float4*)&Bs[brow][bcol] = b;
        __syncthreads();
        #pragma unroll
        for (int kk = 0; kk < 8; kk++) {
            float ar[8], br[8];
            *(float4*)(ar + 0) = *(const float4*)&As[kk][tm + 0];
            *(float4*)(ar + 4) = *(const float4*)&As[kk][tm + 4];
            *(float4*)(br + 0) = *(const float4*)&Bs[kk][tn + 0];
            *(float4*)(br + 4) = *(const float4*)&Bs[kk][tn + 4];
            #pragma unroll
            for (int i = 0; i < 8; i++)
                #pragma unroll
                for (int j = 0; j < 8; j++)
                    acc[i][j] = fmaf(ar[i], br[j], acc[i][j]);
        }
        __syncthreads();
    }

    // Epilogue: bias + scatter to (b,h,t,d); q gets 1/sqrt(64)=0.125 folded in
    #pragma unroll
    for (int i = 0; i < 8; i++) {
        const int m = m0 + tm + i;
        const int bidx = m >> 11;        // / T
        const int t = m & (TT - 1);
        #pragma unroll
        for (int j = 0; j < 8; j++) {
            const int n = n0 + tn + j;
            float val = acc[i][j] + bias[n];
            const int s = n >> 10;            // 0:q 1:k 2:v
            const int h = (n & 1023) >> 6;
            const int d = n & 63;
            const size_t idx = (((size_t)(bidx * HH + h)) * TT + t) * DD + d;
            if (s == 0)      g_q[idx] = val * 0.125f;
            else if (s == 1) g_k[idx] = val;
            else             g_v[idx] = val;
        }
    }
}

// ---------------------------------------------------------------------------
// Causal flash attention. Block = 64 threads = 64 query rows of one tile.
// Each thread: q row + accumulator in registers. K/V tiles staged in smem.
// ---------------------------------------------------------------------------
__global__ __launch_bounds__(64) void attn_kernel()
{
    __shared__ float Ks[64][64];
    __shared__ float Vs[64][64];
    const int qt  = blockIdx.x;   // query tile 0..31
    const int h   = blockIdx.y;
    const int b   = blockIdx.z;
    const int tid = threadIdx.x;  // 0..63

    const size_t head_off = ((size_t)(b * HH + h)) * TT * DD;
    const float* __restrict__ qbase = g_q + head_off;
    const float* __restrict__ kbase = g_k + head_off;
    const float* __restrict__ vbase = g_v + head_off;

    const int q_idx = qt * 64 + tid;

    float qreg[64];
    #pragma unroll
    for (int d = 0; d < 64; d += 4) {
        float4 v = *(const float4*)(qbase + (size_t)q_idx * DD + d);
        qreg[d] = v.x; qreg[d + 1] = v.y; qreg[d + 2] = v.z; qreg[d + 3] = v.w;
    }

    float mrow = -1e30f, l = 0.f;
    float acc[64];
    #pragma unroll
    for (int d = 0; d < 64; d++) acc[d] = 0.f;

    for (int jt = 0; jt <= qt; jt++) {
        // stage K/V tile (coalesced; smem stores conflict-free: bank = tid)
        #pragma unroll 8
        for (int r = 0; r < 64; r++) {
            Ks[r][tid] = kbase[(size_t)(jt * 64 + r) * DD + tid];
            Vs[r][tid] = vbase[(size_t)(jt * 64 + r) * DD + tid];
        }
        __syncthreads();

        const int nvalid = (jt == qt) ? (tid + 1) : 64;

        float s[64];
        float mt = mrow;
        #pragma unroll
        for (int j = 0; j < 64; j++) {
            float s0 = 0.f, s1 = 0.f, s2 = 0.f, s3 = 0.f;
            #pragma unroll
            for (int d = 0; d < 64; d += 4) {
                s0 = fmaf(qreg[d + 0], Ks[j][d + 0], s0);
                s1 = fmaf(qreg[d + 1], Ks[j][d + 1], s1);
                s2 = fmaf(qreg[d + 2], Ks[j][d + 2], s2);
                s3 = fmaf(qreg[d + 3], Ks[j][d + 3], s3);
            }
            float sum = (s0 + s1) + (s2 + s3);
            s[j] = (j < nvalid) ? sum : -1e30f;
            mt = fmaxf(mt, s[j]);
        }

        const float corr = __expf(mrow - mt);
        mrow = mt;
        l *= corr;
        #pragma unroll
        for (int d = 0; d < 64; d++) acc[d] *= corr;

        #pragma unroll
        for (int j = 0; j < 64; j++) {
            const float p = __expf(s[j] - mt);
            l += p;
            #pragma unroll
            for (int d = 0; d < 64; d++)
                acc[d] = fmaf(p, Vs[j][d], acc[d]);
        }
        __syncthreads();
    }

    const float inv = 1.f / l;
    float* obase = g_o + ((size_t)(b * TT) + q_idx) * CC + h * DD;
    #pragma unroll
    for (int d = 0; d < 64; d += 4) {
        float4 o4;
        o4.x = acc[d + 0] * inv;
        o4.y = acc[d + 1] * inv;
        o4.z = acc[d + 2] * inv;
        o4.w = acc[d + 3] * inv;
        *(float4*)(obase + d) = o4;
    }
}

// ---------------------------------------------------------------------------
// Output projection: out = g_o @ w_proj + b_proj
// ---------------------------------------------------------------------------
__global__ __launch_bounds__(256) void proj_gemm(
    const float* __restrict__ w, const float* __restrict__ bias,
    float* __restrict__ out)
{
    __shared__ float As[8][128];
    __shared__ float Bs[8][128];
    const int tid = threadIdx.x;
    const int m0 = blockIdx.y * 128;
    const int n0 = blockIdx.x * 128;
    const int tm = (tid >> 4) * 8;
    const int tn = (tid & 15) * 8;

    const int arow = tid >> 1, acol = (tid & 1) * 4;
    const int brow = tid >> 5, bcol = (tid & 31) * 4;

    float acc[8][8];
    #pragma unroll
    for (int i = 0; i < 8; i++)
        #pragma unroll
        for (int j = 0; j < 8; j++) acc[i][j] = 0.f;

    for (int k0 = 0; k0 < CC; k0 += 8) {
        float4 a = *(const float4*)(g_o + (size_t)(m0 + arow) * CC + k0 + acol);
        As[acol + 0][arow] = a.x;
        As[acol + 1][arow] = a.y;
        As[acol + 2][arow] = a.z;
        As[acol + 3][arow] = a.w;
        float4 b = *(const float4*)(w + (size_t)(k0 + brow) * CC + n0 + bcol);
        *(float4*)&Bs[brow][bcol] = b;
        __syncthreads();
        #pragma unroll
        for (int kk = 0; kk < 8; kk++) {
            float ar[8], br[8];
            *(float4*)(ar + 0) = *(const float4*)&As[kk][tm + 0];
            *(float4*)(ar + 4) = *(const float4*)&As[kk][tm + 4];
            *(float4*)(br + 0) = *(const float4*)&Bs[kk][tn + 0];
            *(float4*)(br + 4) = *(const float4*)&Bs[kk][tn + 4];
            #pragma unroll
            for (int i = 0; i < 8; i++)
                #pragma unroll
                for (int j = 0; j < 8; j++)
                    acc[i][j] = fmaf(ar[i], br[j], acc[i][j]);
        }
        __syncthreads();
    }

    #pragma unroll
    for (int i = 0; i < 8; i++) {
        const int m = m0 + tm + i;
        #pragma unroll
        for (int j = 0; j < 8; j += 4) {
            const int n = n0 + tn + j;
            float4 o4;
            o4.x = acc[i][j + 0] + bias[n + 0];
            o4.y = acc[i][j + 1] + bias[n + 1];
            o4.z = acc[i][j + 2] + bias[n + 2];
            o4.w = acc[i][j + 3] + bias[n + 3];
            *(float4*)(out + (size_t)m * CC + n) = o4;
        }
    }
}

extern "C" void kernel_launch(void* const* d_in, const int* in_sizes, int n_in,
                              void* d_out, int out_size)
{
    const float* x      = (const float*)d_in[0];
    const float* w_qkv  = (const float*)d_in[1];
    const float* b_qkv  = (const float*)d_in[2];
    const float* w_proj = (const float*)d_in[3];
    const float* b_proj = (const float*)d_in[4];
    float* out = (float*)d_out;

    dim3 g1(NQKV / 128, MROWS / 128);   // (24, 64)
    qkv_gemm<<<g1, 256>>>(x, w_qkv, b_qkv);

    dim3 g2(TT / 64, HH, BB);           // (32, 16, 4)
    attn_kernel<<<g2, 64>>>();

    dim3 g3(CC / 128, MROWS / 128);     // (8, 64)
    proj_gemm<<<g3, 256>>>(w_proj, b_proj, out);
}

// round 2
// speedup vs baseline: 1.3137x; 1.3137x over previous
#include <cuda_runtime.h>
#include <math.h>

#define BB 4
#define TT 2048
#define CC 1024
#define HH 16
#define DD 64
#define MROWS (BB*TT)     // 8192
#define NQKV  (3*CC)      // 3072

// Scratch (device globals — allocation-free per harness rules)
__device__ float g_q[BB*HH*TT*DD];   // (b,h,t,d), pre-scaled by 1/sqrt(D)
__device__ float g_k[BB*HH*TT*DD];
__device__ float g_v[BB*HH*TT*DD];
__device__ float g_o[MROWS*CC];      // (b*T+t, h*D+d)

__device__ __forceinline__ float to_tf32(float x) {
    float y;
    asm("cvt.rna.tf32.f32 %0, %1;" : "=f"(y) : "f"(x));
    return y;
}

__device__ __forceinline__ void mma_tf32(float d[4], const float a[4], const float b[2]) {
    asm volatile(
        "mma.sync.aligned.m16n8k8.row.col.f32.tf32.tf32.f32 "
        "{%0,%1,%2,%3}, {%4,%5,%6,%7}, {%8,%9}, {%0,%1,%2,%3};\n"
        : "+f"(d[0]), "+f"(d[1]), "+f"(d[2]), "+f"(d[3])
        : "r"(__float_as_uint(a[0])), "r"(__float_as_uint(a[1])),
          "r"(__float_as_uint(a[2])), "r"(__float_as_uint(a[3])),
          "r"(__float_as_uint(b[0])), "r"(__float_as_uint(b[1])));
}

#define SPITCH 136   // floats; bank = (k*8 + g) % 32 -> conflict-free frag loads

// ---------------------------------------------------------------------------
// tf32 tensor-core GEMM: C = A(M x 1024) @ Bw(1024 x N) + bias
// mode 0: QKV epilogue (scatter to g_q/g_k/g_v, q scaled by 0.125)
// mode 1: proj epilogue (A is g_o, write to out)
// Block 128x128, BK=16 double-buffered, 8 warps (2x4), warp tile 64x32.
// ---------------------------------------------------------------------------
__global__ __launch_bounds__(256) void gemm_tf32(
    const float* __restrict__ Ain, const float* __restrict__ Bw,
    const float* __restrict__ bias, float* __restrict__ out,
    int N, int mode)
{
    __shared__ float As[2][16 * SPITCH];
    __shared__ float Bs[2][16 * SPITCH];

    const float* __restrict__ A = (mode == 1) ? (const float*)g_o : Ain;

    const int tid  = threadIdx.x;
    const int lane = tid & 31;
    const int wid  = tid >> 5;
    const int g    = lane >> 2;
    const int t4   = lane & 3;
    const int warp_m = (wid >> 2) * 64;
    const int warp_n = (wid & 3) * 32;
    const int m0 = blockIdx.y * 128;
    const int n0 = blockIdx.x * 128;

    const int ar = tid >> 2;          // 0..63  (A rows, +64 for second half)
    const int ak = (tid & 3) * 4;     // A k-offset (float4)
    const int br = tid >> 4;          // 0..15  (B row = k)
    const int bc = (tid & 15) * 4;    // B col (float4), second at +64

    float acc[4][4][4];
    #pragma unroll
    for (int i = 0; i < 4; i++)
        #pragma unroll
        for (int j = 0; j < 4; j++)
            #pragma unroll
            for (int r = 0; r < 4; r++) acc[i][j][r] = 0.f;

    // tile loader: global -> smem (tf32-rounded). A transposed to [k][m].
    auto load_tile = [&](int k0, int buf) {
        #pragma unroll
        for (int h = 0; h < 2; h++) {
            const int m = ar + h * 64;
            float4 a4 = *(const float4*)(A + (size_t)(m0 + m) * CC + k0 + ak);
            As[buf][(ak + 0) * SPITCH + m] = to_tf32(a4.x);
            As[buf][(ak + 1) * SPITCH + m] = to_tf32(a4.y);
            As[buf][(ak + 2) * SPITCH + m] = to_tf32(a4.z);
            As[buf][(ak + 3) * SPITCH + m] = to_tf32(a4.w);
        }
        #pragma unroll
        for (int h = 0; h < 2; h++) {
            const int n = bc + h * 64;
            float4 b4 = *(const float4*)(Bw + (size_t)(k0 + br) * N + n0 + n);
            b4.x = to_tf32(b4.x); b4.y = to_tf32(b4.y);
            b4.z = to_tf32(b4.z); b4.w = to_tf32(b4.w);
            *(float4*)&Bs[buf][br * SPITCH + n] = b4;
        }
    };

    load_tile(0, 0);
    __syncthreads();

    for (int k0 = 0; k0 < CC; k0 += 16) {
        const int buf = (k0 >> 4) & 1;
        if (k0 + 16 < CC) load_tile(k0 + 16, buf ^ 1);

        #pragma unroll
        for (int ks = 0; ks < 2; ks++) {
            const int kb = ks * 8;
            float af[4][4], bf[4][2];
            #pragma unroll
            for (int mt = 0; mt < 4; mt++) {
                const int m = warp_m + mt * 16 + g;
                af[mt][0] = As[buf][(kb + t4) * SPITCH + m];
                af[mt][1] = As[buf][(kb + t4) * SPITCH + m + 8];
                af[mt][2] = As[buf][(kb + t4 + 4) * SPITCH + m];
                af[mt][3] = As[buf][(kb + t4 + 4) * SPITCH + m + 8];
            }
            #pragma unroll
            for (int nt = 0; nt < 4; nt++) {
                const int n = warp_n + nt * 8 + g;
                bf[nt][0] = Bs[buf][(kb + t4) * SPITCH + n];
                bf[nt][1] = Bs[buf][(kb + t4 + 4) * SPITCH + n];
            }
            #pragma unroll
            for (int mt = 0; mt < 4; mt++)
                #pragma unroll
                for (int nt = 0; nt < 4; nt++)
                    mma_tf32(acc[mt][nt], af[mt], bf[nt]);
        }
        __syncthreads();
    }

    // Epilogue. C fragment: regs {0,1} at row g, cols 2*t4..2*t4+1; {2,3} at row g+8.
    #pragma unroll
    for (int mt = 0; mt < 4; mt++) {
        #pragma unroll
        for (int half = 0; half < 2; half++) {
            const int m = m0 + warp_m + mt * 16 + g + half * 8;
            #pragma unroll
            for (int nt = 0; nt < 4; nt++) {
                const int n = n0 + warp_n + nt * 8 + t4 * 2;
                float v0 = acc[mt][nt][half * 2 + 0] + bias[n];
                float v1 = acc[mt][nt][half * 2 + 1] + bias[n + 1];
                if (mode == 1) {
                    float2 o2 = make_float2(v0, v1);
                    *(float2*)(out + (size_t)m * CC + n) = o2;
                } else {
                    const int s = n >> 10;            // 0:q 1:k 2:v
                    const int h = (n & 1023) >> 6;
                    const int d = n & 63;             // even, d+1 same head
                    const int bidx = m >> 11;
                    const int t = m & (TT - 1);
                    const size_t idx = (((size_t)(bidx * HH + h)) * TT + t) * DD + d;
                    float2 o2;
                    if (s == 0) { o2 = make_float2(v0 * 0.125f, v1 * 0.125f);
                                  *(float2*)(g_q + idx) = o2; }
                    else if (s == 1) { o2 = make_float2(v0, v1);
                                  *(float2*)(g_k + idx) = o2; }
                    else        { o2 = make_float2(v0, v1);
                                  *(float2*)(g_v + idx) = o2; }
                }
            }
        }
    }
}

// ---------------------------------------------------------------------------
// Causal flash attention (fp32 FFMA). Block = 64 threads = 64 query rows.
// ---------------------------------------------------------------------------
__global__ __launch_bounds__(64) void attn_kernel()
{
    __shared__ float Ks[64][64];
    __shared__ float Vs[64][64];
    const int qt  = blockIdx.x;
    const int h   = blockIdx.y;
    const int b   = blockIdx.z;
    const int tid = threadIdx.x;

    const size_t head_off = ((size_t)(b * HH + h)) * TT * DD;
    const float* __restrict__ qbase = g_q + head_off;
    const float* __restrict__ kbase = g_k + head_off;
    const float* __restrict__ vbase = g_v + head_off;

    const int q_idx = qt * 64 + tid;

    float qreg[64];
    #pragma unroll
    for (int d = 0; d < 64; d += 4) {
        float4 v = *(const float4*)(qbase + (size_t)q_idx * DD + d);
        qreg[d] = v.x; qreg[d + 1] = v.y; qreg[d + 2] = v.z; qreg[d + 3] = v.w;
    }

    float mrow = -1e30f, l = 0.f;
    float acc[64];
    #pragma unroll
    for (int d = 0; d < 64; d++) acc[d] = 0.f;

    for (int jt = 0; jt <= qt; jt++) {
        #pragma unroll 8
        for (int r = 0; r < 64; r++) {
            Ks[r][tid] = kbase[(size_t)(jt * 64 + r) * DD + tid];
            Vs[r][tid] = vbase[(size_t)(jt * 64 + r) * DD + tid];
        }
        __syncthreads();

        const int nvalid = (jt == qt) ? (tid + 1) : 64;

        float s[64];
        float mt = mrow;
        #pragma unroll
        for (int j = 0; j < 64; j++) {
            float s0 = 0.f, s1 = 0.f, s2 = 0.f, s3 = 0.f;
            #pragma unroll
            for (int d = 0; d < 64; d += 4) {
                s0 = fmaf(qreg[d + 0], Ks[j][d + 0], s0);
                s1 = fmaf(qreg[d + 1], Ks[j][d + 1], s1);
                s2 = fmaf(qreg[d + 2], Ks[j][d + 2], s2);
                s3 = fmaf(qreg[d + 3], Ks[j][d + 3], s3);
            }
            float sum = (s0 + s1) + (s2 + s3);
            s[j] = (j < nvalid) ? sum : -1e30f;
            mt = fmaxf(mt, s[j]);
        }

        const float corr = __expf(mrow - mt);
        mrow = mt;
        l *= corr;
        #pragma unroll
        for (int d = 0; d < 64; d++) acc[d] *= corr;

        #pragma unroll
        for (int j = 0; j < 64; j++) {
            const float p = __expf(s[j] - mt);
            l += p;
            #pragma unroll
            for (int d = 0; d < 64; d++)
                acc[d] = fmaf(p, Vs[j][d], acc[d]);
        }
        __syncthreads();
    }

    const float inv = 1.f / l;
    float* obase = g_o + ((size_t)(b * TT) + q_idx) * CC + h * DD;
    #pragma unroll
    for (int d = 0; d < 64; d += 4) {
        float4 o4;
        o4.x = acc[d + 0] * inv;
        o4.y = acc[d + 1] * inv;
        o4.z = acc[d + 2] * inv;
        o4.w = acc[d + 3] * inv;
        *(float4*)(obase + d) = o4;
    }
}

extern "C" void kernel_launch(void* const* d_in, const int* in_sizes, int n_in,
                              void* d_out, int out_size)
{
    const float* x      = (const float*)d_in[0];
    const float* w_qkv  = (const float*)d_in[1];
    const float* b_qkv  = (const float*)d_in[2];
    const float* w_proj = (const float*)d_in[3];
    const float* b_proj = (const float*)d_in[4];
    float* out = (float*)d_out;

    dim3 g1(NQKV / 128, MROWS / 128);   // (24, 64)
    gemm_tf32<<<g1, 256>>>(x, w_qkv, b_qkv, nullptr, NQKV, 0);

    dim3 g2(TT / 64, HH, BB);           // (32, 16, 4)
    attn_kernel<<<g2, 64>>>();

    dim3 g3(CC / 128, MROWS / 128);     // (8, 64)
    gemm_tf32<<<g3, 256>>>(nullptr, w_proj, b_proj, out, CC, 1);
}

// round 3
// speedup vs baseline: 3.4517x; 2.6275x over previous
#include <cuda_runtime.h>
#include <math.h>

#define BB 4
#define TT 2048
#define CC 1024
#define HH 16
#define DD 64
#define MROWS (BB*TT)     // 8192
#define NQKV  (3*CC)      // 3072

// Scratch (device globals — allocation-free per harness rules)
__device__ float g_q[BB*HH*TT*DD];   // (b,h,t,d), pre-scaled by 0.125*log2(e)
__device__ float g_k[BB*HH*TT*DD];
__device__ float g_v[BB*HH*TT*DD];
__device__ float g_o[MROWS*CC];      // (b*T+t, h*D+d)

__device__ __forceinline__ float to_tf32(float x) {
    float y;
    asm("cvt.rna.tf32.f32 %0, %1;" : "=f"(y) : "f"(x));
    return y;
}
__device__ __forceinline__ float ex2(float x) {
    float y;
    asm("ex2.approx.ftz.f32 %0, %1;" : "=f"(y) : "f"(x));
    return y;
}

__device__ __forceinline__ void mma_tf32(float d[4], const float a[4], const float b[2]) {
    asm volatile(
        "mma.sync.aligned.m16n8k8.row.col.f32.tf32.tf32.f32 "
        "{%0,%1,%2,%3}, {%4,%5,%6,%7}, {%8,%9}, {%0,%1,%2,%3};\n"
        : "+f"(d[0]), "+f"(d[1]), "+f"(d[2]), "+f"(d[3])
        : "r"(__float_as_uint(a[0])), "r"(__float_as_uint(a[1])),
          "r"(__float_as_uint(a[2])), "r"(__float_as_uint(a[3])),
          "r"(__float_as_uint(b[0])), "r"(__float_as_uint(b[1])));
}

#define SPITCH 136   // gemm smem pitch (floats)

// ---------------------------------------------------------------------------
// tf32 tensor-core GEMM: C = A(M x 1024) @ Bw(1024 x N) + bias
// mode 0: QKV epilogue (scatter to g_q/g_k/g_v, q scaled by 0.125*log2e)
// mode 1: proj epilogue (A is g_o, write to out)
// ---------------------------------------------------------------------------
__global__ __launch_bounds__(256) void gemm_tf32(
    const float* __restrict__ Ain, const float* __restrict__ Bw,
    const float* __restrict__ bias, float* __restrict__ out,
    int N, int mode)
{
    __shared__ float As[2][16 * SPITCH];
    __shared__ float Bs[2][16 * SPITCH];

    const float* __restrict__ A = (mode == 1) ? (const float*)g_o : Ain;

    const int tid  = threadIdx.x;
    const int lane = tid & 31;
    const int wid  = tid >> 5;
    const int g    = lane >> 2;
    const int t4   = lane & 3;
    const int warp_m = (wid >> 2) * 64;
    const int warp_n = (wid & 3) * 32;
    const int m0 = blockIdx.y * 128;
    const int n0 = blockIdx.x * 128;

    const int ar = tid >> 2;
    const int ak = (tid & 3) * 4;
    const int br = tid >> 4;
    const int bc = (tid & 15) * 4;

    float acc[4][4][4];
    #pragma unroll
    for (int i = 0; i < 4; i++)
        #pragma unroll
        for (int j = 0; j < 4; j++)
            #pragma unroll
            for (int r = 0; r < 4; r++) acc[i][j][r] = 0.f;

    auto load_tile = [&](int k0, int buf) {
        #pragma unroll
        for (int h = 0; h < 2; h++) {
            const int m = ar + h * 64;
            float4 a4 = *(const float4*)(A + (size_t)(m0 + m) * CC + k0 + ak);
            As[buf][(ak + 0) * SPITCH + m] = to_tf32(a4.x);
            As[buf][(ak + 1) * SPITCH + m] = to_tf32(a4.y);
            As[buf][(ak + 2) * SPITCH + m] = to_tf32(a4.z);
            As[buf][(ak + 3) * SPITCH + m] = to_tf32(a4.w);
        }
        #pragma unroll
        for (int h = 0; h < 2; h++) {
            const int n = bc + h * 64;
            float4 b4 = *(const float4*)(Bw + (size_t)(k0 + br) * N + n0 + n);
            b4.x = to_tf32(b4.x); b4.y = to_tf32(b4.y);
            b4.z = to_tf32(b4.z); b4.w = to_tf32(b4.w);
            *(float4*)&Bs[buf][br * SPITCH + n] = b4;
        }
    };

    load_tile(0, 0);
    __syncthreads();

    for (int k0 = 0; k0 < CC; k0 += 16) {
        const int buf = (k0 >> 4) & 1;
        if (k0 + 16 < CC) load_tile(k0 + 16, buf ^ 1);

        #pragma unroll
        for (int ks = 0; ks < 2; ks++) {
            const int kb = ks * 8;
            float af[4][4], bf[4][2];
            #pragma unroll
            for (int mt = 0; mt < 4; mt++) {
                const int m = warp_m + mt * 16 + g;
                af[mt][0] = As[buf][(kb + t4) * SPITCH + m];
                af[mt][1] = As[buf][(kb + t4) * SPITCH + m + 8];
                af[mt][2] = As[buf][(kb + t4 + 4) * SPITCH + m];
                af[mt][3] = As[buf][(kb + t4 + 4) * SPITCH + m + 8];
            }
            #pragma unroll
            for (int nt = 0; nt < 4; nt++) {
                const int n = warp_n + nt * 8 + g;
                bf[nt][0] = Bs[buf][(kb + t4) * SPITCH + n];
                bf[nt][1] = Bs[buf][(kb + t4 + 4) * SPITCH + n];
            }
            #pragma unroll
            for (int mt = 0; mt < 4; mt++)
                #pragma unroll
                for (int nt = 0; nt < 4; nt++)
                    mma_tf32(acc[mt][nt], af[mt], bf[nt]);
        }
        __syncthreads();
    }

    #pragma unroll
    for (int mt = 0; mt < 4; mt++) {
        #pragma unroll
        for (int half = 0; half < 2; half++) {
            const int m = m0 + warp_m + mt * 16 + g + half * 8;
            #pragma unroll
            for (int nt = 0; nt < 4; nt++) {
                const int n = n0 + warp_n + nt * 8 + t4 * 2;
                float v0 = acc[mt][nt][half * 2 + 0] + bias[n];
                float v1 = acc[mt][nt][half * 2 + 1] + bias[n + 1];
                if (mode == 1) {
                    *(float2*)(out + (size_t)m * CC + n) = make_float2(v0, v1);
                } else {
                    const int s = n >> 10;            // 0:q 1:k 2:v
                    const int h = (n & 1023) >> 6;
                    const int d = n & 63;
                    const int bidx = m >> 11;
                    const int t = m & (TT - 1);
                    const size_t idx = (((size_t)(bidx * HH + h)) * TT + t) * DD + d;
                    const float QS = 0.125f * 1.44269504f;  // 1/sqrt(D) * log2(e)
                    if (s == 0)      *(float2*)(g_q + idx) = make_float2(v0 * QS, v1 * QS);
                    else if (s == 1) *(float2*)(g_k + idx) = make_float2(v0, v1);
                    else             *(float2*)(g_v + idx) = make_float2(v0, v1);
                }
            }
        }
    }
}

// ---------------------------------------------------------------------------
// Tensor-core causal flash attention (tf32 mma, online softmax in 2^ domain).
// CTA = 128 threads (4 warps) per 64-query tile. Warp owns a 16-row strip.
// P.V uses hi/lo split of P (2 mmas) to keep accuracy budget.
// ---------------------------------------------------------------------------
#define KPITCH 72

__global__ __launch_bounds__(128) void attn_tc()
{
    __shared__ float Ks[64 * KPITCH];
    __shared__ float Vs[64 * KPITCH];

    const int qt  = (int)gridDim.x - 1 - (int)blockIdx.x;  // heavy tiles first
    const int h   = blockIdx.y;
    const int b   = blockIdx.z;
    const int tid  = threadIdx.x;
    const int lane = tid & 31;
    const int w    = tid >> 5;
    const int g    = lane >> 2;
    const int t4   = lane & 3;

    const size_t head_off = ((size_t)(b * HH + h)) * TT * DD;
    const float* __restrict__ qb = g_q + head_off;
    const float* __restrict__ kb = g_k + head_off;
    const float* __restrict__ vb = g_v + head_off;

    // Q fragments in registers for entire CTA lifetime (pre-scaled in gmem)
    float qf[8][4];
    {
        const int r0 = qt * 64 + w * 16 + g;
        #pragma unroll
        for (int kc = 0; kc < 8; kc++) {
            qf[kc][0] = to_tf32(qb[(size_t)r0 * DD + kc * 8 + t4]);
            qf[kc][1] = to_tf32(qb[(size_t)(r0 + 8) * DD + kc * 8 + t4]);
            qf[kc][2] = to_tf32(qb[(size_t)r0 * DD + kc * 8 + t4 + 4]);
            qf[kc][3] = to_tf32(qb[(size_t)(r0 + 8) * DD + kc * 8 + t4 + 4]);
        }
    }

    float o[8][4];
    #pragma unroll
    for (int nt = 0; nt < 8; nt++)
        #pragma unroll
        for (int r = 0; r < 4; r++) o[nt][r] = 0.f;
    float m0 = -1e30f, m1 = -1e30f, l0 = 0.f, l1 = 0.f;

    const int ldr = tid >> 1;            // K/V stage: row 0..63
    const int ldc = (tid & 1) * 32;      // col half

    for (int jt = 0; jt <= qt; jt++) {
        // ---- stage K/V tile into smem (tf32-rounded) ----
        #pragma unroll
        for (int c = 0; c < 32; c += 4) {
            float4 k4 = *(const float4*)(kb + (size_t)(jt * 64 + ldr) * DD + ldc + c);
            k4.x = to_tf32(k4.x); k4.y = to_tf32(k4.y);
            k4.z = to_tf32(k4.z); k4.w = to_tf32(k4.w);
            *(float4*)&Ks[ldr * KPITCH + ldc + c] = k4;
            float4 v4 = *(const float4*)(vb + (size_t)(jt * 64 + ldr) * DD + ldc + c);
            v4.x = to_tf32(v4.x); v4.y = to_tf32(v4.y);
            v4.z = to_tf32(v4.z); v4.w = to_tf32(v4.w);
            *(float4*)&Vs[ldr * KPITCH + ldc + c] = v4;
        }
        __syncthreads();

        // ---- S = Q @ K^T  (warp strip 16 x 64) ----
        float s[8][4];
        #pragma unroll
        for (int nt = 0; nt < 8; nt++)
            #pragma unroll
            for (int r = 0; r < 4; r++) s[nt][r] = 0.f;

        #pragma unroll
        for (int kc = 0; kc < 8; kc++) {
            #pragma unroll
            for (int nt = 0; nt < 8; nt++) {
                float bk[2];
                bk[0] = Ks[(nt * 8 + g) * KPITCH + kc * 8 + t4];
                bk[1] = Ks[(nt * 8 + g) * KPITCH + kc * 8 + t4 + 4];
                mma_tf32(s[nt], qf[kc], bk);
            }
        }

        // ---- causal mask on diagonal tile ----
        if (jt == qt) {
            const int rlo = w * 16 + g;
            const int rhi = rlo + 8;
            #pragma unroll
            for (int nt = 0; nt < 8; nt++) {
                const int col = nt * 8 + 2 * t4;
                if (col     > rlo) s[nt][0] = -1e30f;
                if (col + 1 > rlo) s[nt][1] = -1e30f;
                if (col     > rhi) s[nt][2] = -1e30f;
                if (col + 1 > rhi) s[nt][3] = -1e30f;
            }
        }

        // ---- online softmax (2^ domain; log2e folded into q) ----
        float mx0 = -1e30f, mx1 = -1e30f;
        #pragma unroll
        for (int nt = 0; nt < 8; nt++) {
            mx0 = fmaxf(mx0, fmaxf(s[nt][0], s[nt][1]));
            mx1 = fmaxf(mx1, fmaxf(s[nt][2], s[nt][3]));
        }
        mx0 = fmaxf(mx0, __shfl_xor_sync(0xffffffffu, mx0, 1));
        mx0 = fmaxf(mx0, __shfl_xor_sync(0xffffffffu, mx0, 2));
        mx1 = fmaxf(mx1, __shfl_xor_sync(0xffffffffu, mx1, 1));
        mx1 = fmaxf(mx1, __shfl_xor_sync(0xffffffffu, mx1, 2));

        const float mn0 = fmaxf(m0, mx0);
        const float mn1 = fmaxf(m1, mx1);
        const float c0 = ex2(m0 - mn0);
        const float c1 = ex2(m1 - mn1);
        m0 = mn0; m1 = mn1;
        l0 *= c0; l1 *= c1;
        #pragma unroll
        for (int nt = 0; nt < 8; nt++) {
            o[nt][0] *= c0; o[nt][1] *= c0;
            o[nt][2] *= c1; o[nt][3] *= c1;
        }

        float r0 = 0.f, r1 = 0.f;
        #pragma unroll
        for (int nt = 0; nt < 8; nt++) {
            s[nt][0] = ex2(s[nt][0] - mn0);
            s[nt][1] = ex2(s[nt][1] - mn0);
            s[nt][2] = ex2(s[nt][2] - mn1);
            s[nt][3] = ex2(s[nt][3] - mn1);
            r0 += s[nt][0] + s[nt][1];
            r1 += s[nt][2] + s[nt][3];
        }
        r0 += __shfl_xor_sync(0xffffffffu, r0, 1);
        r0 += __shfl_xor_sync(0xffffffffu, r0, 2);
        r1 += __shfl_xor_sync(0xffffffffu, r1, 1);
        r1 += __shfl_xor_sync(0xffffffffu, r1, 2);
        l0 += r0; l1 += r1;

        // ---- O += P @ V  (P gathered C->A via shuffles, hi/lo split) ----
        const int srcA = (lane & ~3) + (t4 >> 1);
        const int srcB = srcA + 2;
        const bool par = (t4 & 1);
        #pragma unroll
        for (int kc = 0; kc < 8; kc++) {
            float x0 = __shfl_sync(0xffffffffu, s[kc][0], srcA);
            float x1 = __shfl_sync(0xffffffffu, s[kc][1], srcA);
            float x2 = __shfl_sync(0xffffffffu, s[kc][2], srcA);
            float x3 = __shfl_sync(0xffffffffu, s[kc][3], srcA);
            float y0 = __shfl_sync(0xffffffffu, s[kc][0], srcB);
            float y1 = __shfl_sync(0xffffffffu, s[kc][1], srcB);
            float y2 = __shfl_sync(0xffffffffu, s[kc][2], srcB);
            float y3 = __shfl_sync(0xffffffffu, s[kc][3], srcB);
            const float pa0 = par ? x1 : x0;   // P[g  ][kc*8+t4  ]
            const float pa1 = par ? x3 : x2;   // P[g+8][kc*8+t4  ]
            const float pa2 = par ? y1 : y0;   // P[g  ][kc*8+t4+4]
            const float pa3 = par ? y3 : y2;   // P[g+8][kc*8+t4+4]
            float ah[4] = {to_tf32(pa0), to_tf32(pa1), to_tf32(pa2), to_tf32(pa3)};
            float al[4] = {to_tf32(pa0 - ah[0]), to_tf32(pa1 - ah[1]),
                           to_tf32(pa2 - ah[2]), to_tf32(pa3 - ah[3])};
            #pragma unroll
            for (int nt = 0; nt < 8; nt++) {
                float bv[2];
                bv[0] = Vs[(kc * 8 + t4) * KPITCH + nt * 8 + g];
                bv[1] = Vs[(kc * 8 + t4 + 4) * KPITCH + nt * 8 + g];
                mma_tf32(o[nt], ah, bv);
                mma_tf32(o[nt], al, bv);
            }
        }
        __syncthreads();
    }

    // ---- epilogue: normalize + store to g_o (row-major (b*T+t, h*64+d)) ----
    const float i0 = 1.f / l0;
    const float i1 = 1.f / l1;
    const int qrow = qt * 64 + w * 16;
    float* ob = g_o + ((size_t)(b * TT) + qrow) * CC + h * DD;
    #pragma unroll
    for (int nt = 0; nt < 8; nt++) {
        const int d = nt * 8 + 2 * t4;
        *(float2*)(ob + (size_t)g * CC + d)       = make_float2(o[nt][0] * i0, o[nt][1] * i0);
        *(float2*)(ob + (size_t)(g + 8) * CC + d) = make_float2(o[nt][2] * i1, o[nt][3] * i1);
    }
}

extern "C" void kernel_launch(void* const* d_in, const int* in_sizes, int n_in,
                              void* d_out, int out_size)
{
    const float* x      = (const float*)d_in[0];
    const float* w_qkv  = (const float*)d_in[1];
    const float* b_qkv  = (const float*)d_in[2];
    const float* w_proj = (const float*)d_in[3];
    const float* b_proj = (const float*)d_in[4];
    float* out = (float*)d_out;

    dim3 g1(NQKV / 128, MROWS / 128);   // (24, 64)
    gemm_tf32<<<g1, 256>>>(x, w_qkv, b_qkv, nullptr, NQKV, 0);

    dim3 g2(TT / 64, HH, BB);           // (32, 16, 4)
    attn_tc<<<g2, 128>>>();

    dim3 g3(CC / 128, MROWS / 128);     // (8, 64)
    gemm_tf32<<<g3, 256>>>(nullptr, w_proj, b_proj, out, CC, 1);
}

// round 4
// speedup vs baseline: 3.8287x; 1.1092x over previous
#include <cuda_runtime.h>
#include <math.h>

#define BB 4
#define TT 2048
#define CC 1024
#define HH 16
#define DD 64
#define MROWS (BB*TT)     // 8192
#define NQKV  (3*CC)      // 3072

// Scratch (device globals — allocation-free per harness rules)
__device__ float g_q[BB*HH*TT*DD];   // (b,h,t,d), pre-scaled by 0.125*log2(e)
__device__ float g_k[BB*HH*TT*DD];
__device__ float g_v[BB*HH*TT*DD];
__device__ float g_o[MROWS*CC];      // (b*T+t, h*D+d)

__device__ __forceinline__ float to_tf32(float x) {
    float y;
    asm("cvt.rna.tf32.f32 %0, %1;" : "=f"(y) : "f"(x));
    return y;
}
__device__ __forceinline__ float ex2(float x) {
    float y;
    asm("ex2.approx.ftz.f32 %0, %1;" : "=f"(y) : "f"(x));
    return y;
}

__device__ __forceinline__ void mma_tf32(float d[4], const float a[4], const float b[2]) {
    asm volatile(
        "mma.sync.aligned.m16n8k8.row.col.f32.tf32.tf32.f32 "
        "{%0,%1,%2,%3}, {%4,%5,%6,%7}, {%8,%9}, {%0,%1,%2,%3};\n"
        : "+f"(d[0]), "+f"(d[1]), "+f"(d[2]), "+f"(d[3])
        : "r"(__float_as_uint(a[0])), "r"(__float_as_uint(a[1])),
          "r"(__float_as_uint(a[2])), "r"(__float_as_uint(a[3])),
          "r"(__float_as_uint(b[0])), "r"(__float_as_uint(b[1])));
}

#define SPITCH 136   // gemm smem pitch (floats)

// ---------------------------------------------------------------------------
// tf32 tensor-core GEMM with register-staged double buffering.
// C = A(M x 1024) @ Bw(1024 x N) + bias
// mode 0: QKV epilogue (scatter to g_q/g_k/g_v, q scaled by 0.125*log2e)
// mode 1: proj epilogue (A is g_o, write to out)
// ---------------------------------------------------------------------------
__global__ __launch_bounds__(256) void gemm_tf32(
    const float* __restrict__ Ain, const float* __restrict__ Bw,
    const float* __restrict__ bias, float* __restrict__ out,
    int N, int mode)
{
    __shared__ float As[2][16 * SPITCH];
    __shared__ float Bs[2][16 * SPITCH];

    const float* __restrict__ A = (mode == 1) ? (const float*)g_o : Ain;

    const int tid  = threadIdx.x;
    const int lane = tid & 31;
    const int wid  = tid >> 5;
    const int g    = lane >> 2;
    const int t4   = lane & 3;
    const int warp_m = (wid >> 2) * 64;
    const int warp_n = (wid & 3) * 32;
    const int m0 = blockIdx.y * 128;
    const int n0 = blockIdx.x * 128;

    const int ar = tid >> 2;
    const int ak = (tid & 3) * 4;
    const int br = tid >> 4;
    const int bc = (tid & 15) * 4;

    float acc[4][4][4];
    #pragma unroll
    for (int i = 0; i < 4; i++)
        #pragma unroll
        for (int j = 0; j < 4; j++)
            #pragma unroll
            for (int r = 0; r < 4; r++) acc[i][j][r] = 0.f;

    float4 a_s[2], b_s[2];

    auto ldg_tile = [&](int k0) {
        a_s[0] = *(const float4*)(A + (size_t)(m0 + ar) * CC + k0 + ak);
        a_s[1] = *(const float4*)(A + (size_t)(m0 + ar + 64) * CC + k0 + ak);
        b_s[0] = *(const float4*)(Bw + (size_t)(k0 + br) * N + n0 + bc);
        b_s[1] = *(const float4*)(Bw + (size_t)(k0 + br) * N + n0 + bc + 64);
    };
    auto sts_tile = [&](int buf) {
        #pragma unroll
        for (int h = 0; h < 2; h++) {
            const int m = ar + h * 64;
            const float4 a4 = a_s[h];
            As[buf][(ak + 0) * SPITCH + m] = to_tf32(a4.x);
            As[buf][(ak + 1) * SPITCH + m] = to_tf32(a4.y);
            As[buf][(ak + 2) * SPITCH + m] = to_tf32(a4.z);
            As[buf][(ak + 3) * SPITCH + m] = to_tf32(a4.w);
        }
        #pragma unroll
        for (int h = 0; h < 2; h++) {
            float4 b4 = b_s[h];
            b4.x = to_tf32(b4.x); b4.y = to_tf32(b4.y);
            b4.z = to_tf32(b4.z); b4.w = to_tf32(b4.w);
            *(float4*)&Bs[buf][br * SPITCH + bc + h * 64] = b4;
        }
    };

    ldg_tile(0);
    sts_tile(0);
    __syncthreads();

    for (int k0 = 0; k0 < CC; k0 += 16) {
        const int buf = (k0 >> 4) & 1;
        const bool pf = (k0 + 16) < CC;
        if (pf) ldg_tile(k0 + 16);       // LDG latency hidden behind mmas

        #pragma unroll
        for (int ks = 0; ks < 2; ks++) {
            const int kb = ks * 8;
            float af[4][4], bf[4][2];
            #pragma unroll
            for (int mt = 0; mt < 4; mt++) {
                const int m = warp_m + mt * 16 + g;
                af[mt][0] = As[buf][(kb + t4) * SPITCH + m];
                af[mt][1] = As[buf][(kb + t4) * SPITCH + m + 8];
                af[mt][2] = As[buf][(kb + t4 + 4) * SPITCH + m];
                af[mt][3] = As[buf][(kb + t4 + 4) * SPITCH + m + 8];
            }
            #pragma unroll
            for (int nt = 0; nt < 4; nt++) {
                const int n = warp_n + nt * 8 + g;
                bf[nt][0] = Bs[buf][(kb + t4) * SPITCH + n];
                bf[nt][1] = Bs[buf][(kb + t4 + 4) * SPITCH + n];
            }
            #pragma unroll
            for (int mt = 0; mt < 4; mt++)
                #pragma unroll
                for (int nt = 0; nt < 4; nt++)
                    mma_tf32(acc[mt][nt], af[mt], bf[nt]);
        }

        if (pf) sts_tile(buf ^ 1);
        __syncthreads();
    }

    #pragma unroll
    for (int mt = 0; mt < 4; mt++) {
        #pragma unroll
        for (int half = 0; half < 2; half++) {
            const int m = m0 + warp_m + mt * 16 + g + half * 8;
            #pragma unroll
            for (int nt = 0; nt < 4; nt++) {
                const int n = n0 + warp_n + nt * 8 + t4 * 2;
                float v0 = acc[mt][nt][half * 2 + 0] + bias[n];
                float v1 = acc[mt][nt][half * 2 + 1] + bias[n + 1];
                if (mode == 1) {
                    *(float2*)(out + (size_t)m * CC + n) = make_float2(v0, v1);
                } else {
                    const int s = n >> 10;            // 0:q 1:k 2:v
                    const int h = (n & 1023) >> 6;
                    const int d = n & 63;
                    const int bidx = m >> 11;
                    const int t = m & (TT - 1);
                    const size_t idx = (((size_t)(bidx * HH + h)) * TT + t) * DD + d;
                    const float QS = 0.125f * 1.44269504f;  // 1/sqrt(D) * log2(e)
                    if (s == 0)      *(float2*)(g_q + idx) = make_float2(v0 * QS, v1 * QS);
                    else if (s == 1) *(float2*)(g_k + idx) = make_float2(v0, v1);
                    else             *(float2*)(g_v + idx) = make_float2(v0, v1);
                }
            }
        }
    }
}

// ---------------------------------------------------------------------------
// Tensor-core causal flash attention (tf32 mma, online softmax in 2^ domain).
// CTA = 128 threads (4 warps) per 64-query tile. Warp owns a 16-row strip.
// P routed C->A via per-warp smem buffer (2 half-tiles of 32 keys each).
// ---------------------------------------------------------------------------
#define KP 72   // K/V smem pitch (floats)
#define PP 36   // P smem pitch (floats); bank = 4g+t4 -> conflict-free

__global__ __launch_bounds__(128) void attn_tc()
{
    __shared__ float Ks[64 * KP];
    __shared__ float Vs[64 * KP];
    __shared__ float Ps[4][16 * PP];

    const int qt  = (int)gridDim.x - 1 - (int)blockIdx.x;  // heavy tiles first
    const int h   = blockIdx.y;
    const int b   = blockIdx.z;
    const int tid  = threadIdx.x;
    const int lane = tid & 31;
    const int w    = tid >> 5;
    const int g    = lane >> 2;
    const int t4   = lane & 3;

    const size_t head_off = ((size_t)(b * HH + h)) * TT * DD;
    const float* __restrict__ qb = g_q + head_off;
    const float* __restrict__ kb = g_k + head_off;
    const float* __restrict__ vb = g_v + head_off;

    // Q fragments in registers for entire CTA lifetime (pre-scaled in gmem)
    float qf[8][4];
    {
        const int r0 = qt * 64 + w * 16 + g;
        #pragma unroll
        for (int kc = 0; kc < 8; kc++) {
            qf[kc][0] = to_tf32(qb[(size_t)r0 * DD + kc * 8 + t4]);
            qf[kc][1] = to_tf32(qb[(size_t)(r0 + 8) * DD + kc * 8 + t4]);
            qf[kc][2] = to_tf32(qb[(size_t)r0 * DD + kc * 8 + t4 + 4]);
            qf[kc][3] = to_tf32(qb[(size_t)(r0 + 8) * DD + kc * 8 + t4 + 4]);
        }
    }

    float o[8][4];
    #pragma unroll
    for (int nt = 0; nt < 8; nt++)
        #pragma unroll
        for (int r = 0; r < 4; r++) o[nt][r] = 0.f;
    float m0 = -1e30f, m1 = -1e30f, l0 = 0.f, l1 = 0.f;

    const int ldr = tid >> 1;            // K/V stage: row 0..63
    const int ldc = (tid & 1) * 32;      // col half

    float* pb = Ps[w];

    for (int jt = 0; jt <= qt; jt++) {
        // ---- stage K/V tile into smem (tf32-rounded) ----
        #pragma unroll
        for (int c = 0; c < 32; c += 4) {
            float4 k4 = *(const float4*)(kb + (size_t)(jt * 64 + ldr) * DD + ldc + c);
            k4.x = to_tf32(k4.x); k4.y = to_tf32(k4.y);
            k4.z = to_tf32(k4.z); k4.w = to_tf32(k4.w);
            *(float4*)&Ks[ldr * KP + ldc + c] = k4;
            float4 v4 = *(const float4*)(vb + (size_t)(jt * 64 + ldr) * DD + ldc + c);
            v4.x = to_tf32(v4.x); v4.y = to_tf32(v4.y);
            v4.z = to_tf32(v4.z); v4.w = to_tf32(v4.w);
            *(float4*)&Vs[ldr * KP + ldc + c] = v4;
        }
        __syncthreads();

        // ---- S = Q @ K^T  (warp strip 16 x 64) ----
        float s[8][4];
        #pragma unroll
        for (int nt = 0; nt < 8; nt++)
            #pragma unroll
            for (int r = 0; r < 4; r++) s[nt][r] = 0.f;

        #pragma unroll
        for (int kc = 0; kc < 8; kc++) {
            #pragma unroll
            for (int nt = 0; nt < 8; nt++) {
                float bk[2];
                bk[0] = Ks[(nt * 8 + g) * KP + kc * 8 + t4];
                bk[1] = Ks[(nt * 8 + g) * KP + kc * 8 + t4 + 4];
                mma_tf32(s[nt], qf[kc], bk);
            }
        }

        // ---- causal mask on diagonal tile ----
        if (jt == qt) {
            const int rlo = w * 16 + g;
            const int rhi = rlo + 8;
            #pragma unroll
            for (int nt = 0; nt < 8; nt++) {
                const int col = nt * 8 + 2 * t4;
                if (col     > rlo) s[nt][0] = -1e30f;
                if (col + 1 > rlo) s[nt][1] = -1e30f;
                if (col     > rhi) s[nt][2] = -1e30f;
                if (col + 1 > rhi) s[nt][3] = -1e30f;
            }
        }

        // ---- online softmax (2^ domain; log2e folded into q) ----
        float mx0 = -1e30f, mx1 = -1e30f;
        #pragma unroll
        for (int nt = 0; nt < 8; nt++) {
            mx0 = fmaxf(mx0, fmaxf(s[nt][0], s[nt][1]));
            mx1 = fmaxf(mx1, fmaxf(s[nt][2], s[nt][3]));
        }
        mx0 = fmaxf(mx0, __shfl_xor_sync(0xffffffffu, mx0, 1));
        mx0 = fmaxf(mx0, __shfl_xor_sync(0xffffffffu, mx0, 2));
        mx1 = fmaxf(mx1, __shfl_xor_sync(0xffffffffu, mx1, 1));
        mx1 = fmaxf(mx1, __shfl_xor_sync(0xffffffffu, mx1, 2));

        const float mn0 = fmaxf(m0, mx0);
        const float mn1 = fmaxf(m1, mx1);
        const float c0 = ex2(m0 - mn0);
        const float c1 = ex2(m1 - mn1);
        m0 = mn0; m1 = mn1;
        l0 *= c0; l1 *= c1;
        #pragma unroll
        for (int nt = 0; nt < 8; nt++) {
            o[nt][0] *= c0; o[nt][1] *= c0;
            o[nt][2] *= c1; o[nt][3] *= c1;
        }

        float r0 = 0.f, r1 = 0.f;
        #pragma unroll
        for (int nt = 0; nt < 8; nt++) {
            s[nt][0] = ex2(s[nt][0] - mn0);
            s[nt][1] = ex2(s[nt][1] - mn0);
            s[nt][2] = ex2(s[nt][2] - mn1);
            s[nt][3] = ex2(s[nt][3] - mn1);
            r0 += s[nt][0] + s[nt][1];
            r1 += s[nt][2] + s[nt][3];
        }
        r0 += __shfl_xor_sync(0xffffffffu, r0, 1);
        r0 += __shfl_xor_sync(0xffffffffu, r0, 2);
        r1 += __shfl_xor_sync(0xffffffffu, r1, 1);
        r1 += __shfl_xor_sync(0xffffffffu, r1, 2);
        l0 += r0; l1 += r1;

        // ---- O += P @ V  via per-warp smem P buffer, 32 keys per half ----
        #pragma unroll
        for (int half = 0; half < 2; half++) {
            #pragma unroll
            for (int q = 0; q < 4; q++) {
                const int nt = half * 4 + q;
                const int col = q * 8 + 2 * t4;
                *(float2*)&pb[g * PP + col] =
                    make_float2(to_tf32(s[nt][0]), to_tf32(s[nt][1]));
                *(float2*)&pb[(g + 8) * PP + col] =
                    make_float2(to_tf32(s[nt][2]), to_tf32(s[nt][3]));
            }
            __syncwarp();
            #pragma unroll
            for (int kc2 = 0; kc2 < 4; kc2++) {
                const int kc = half * 4 + kc2;   // global key chunk
                float a[4];
                a[0] = pb[g * PP + kc2 * 8 + t4];
                a[1] = pb[(g + 8) * PP + kc2 * 8 + t4];
                a[2] = pb[g * PP + kc2 * 8 + t4 + 4];
                a[3] = pb[(g + 8) * PP + kc2 * 8 + t4 + 4];
                #pragma unroll
                for (int nt = 0; nt < 8; nt++) {
                    float bv[2];
                    bv[0] = Vs[(kc * 8 + t4) * KP + nt * 8 + g];
                    bv[1] = Vs[(kc * 8 + t4 + 4) * KP + nt * 8 + g];
                    mma_tf32(o[nt], a, bv);
                }
            }
            __syncwarp();
        }
        __syncthreads();
    }

    // ---- epilogue: normalize + store to g_o (row-major (b*T+t, h*64+d)) ----
    const float i0 = 1.f / l0;
    const float i1 = 1.f / l1;
    const int qrow = qt * 64 + w * 16;
    float* ob = g_o + ((size_t)(b * TT) + qrow) * CC + h * DD;
    #pragma unroll
    for (int nt = 0; nt < 8; nt++) {
        const int d = nt * 8 + 2 * t4;
        *(float2*)(ob + (size_t)g * CC + d)       = make_float2(o[nt][0] * i0, o[nt][1] * i0);
        *(float2*)(ob + (size_t)(g + 8) * CC + d) = make_float2(o[nt][2] * i1, o[nt][3] * i1);
    }
}

extern "C" void kernel_launch(void* const* d_in, const int* in_sizes, int n_in,
                              void* d_out, int out_size)
{
    const float* x      = (const float*)d_in[0];
    const float* w_qkv  = (const float*)d_in[1];
    const float* b_qkv  = (const float*)d_in[2];
    const float* w_proj = (const float*)d_in[3];
    const float* b_proj = (const float*)d_in[4];
    float* out = (float*)d_out;

    dim3 g1(NQKV / 128, MROWS / 128);   // (24, 64)
    gemm_tf32<<<g1, 256>>>(x, w_qkv, b_qkv, nullptr, NQKV, 0);

    dim3 g2(TT / 64, HH, BB);           // (32, 16, 4)
    attn_tc<<<g2, 128>>>();

    dim3 g3(CC / 128, MROWS / 128);     // (8, 64)
    gemm_tf32<<<g3, 256>>>(nullptr, w_proj, b_proj, out, CC, 1);
}

// round 6
// speedup vs baseline: 4.4169x; 1.1536x over previous
#include <cuda_runtime.h>
#include <math.h>
#include <stdint.h>

#define BB 4
#define TT 2048
#define CC 1024
#define HH 16
#define DD 64
#define MROWS (BB*TT)     // 8192
#define NQKV  (3*CC)      // 3072

// Scratch (device globals — allocation-free per harness rules)
__device__ float g_q[BB*HH*TT*DD];   // tf32-rounded, pre-scaled by 0.125*log2(e)
__device__ float g_k[BB*HH*TT*DD];   // tf32-rounded
__device__ float g_v[BB*HH*TT*DD];   // tf32-rounded
__device__ float g_o[MROWS*CC];      // tf32-rounded attention output
__device__ float g_xr[MROWS*CC];     // tf32-rounded x
__device__ float g_wq[CC*NQKV];      // tf32-rounded w_qkv
__device__ float g_wp[CC*CC];        // tf32-rounded w_proj

__device__ __forceinline__ float to_tf32(float x) {
    float y;
    asm("cvt.rna.tf32.f32 %0, %1;" : "=f"(y) : "f"(x));
    return y;
}
__device__ __forceinline__ float ex2(float x) {
    float y;
    asm("ex2.approx.ftz.f32 %0, %1;" : "=f"(y) : "f"(x));
    return y;
}
__device__ __forceinline__ uint32_t sptr(const void* p) {
    return (uint32_t)__cvta_generic_to_shared(p);
}
__device__ __forceinline__ void cp16(uint32_t s, const void* g) {
    asm volatile("cp.async.cg.shared.global [%0], [%1], 16;\n" :: "r"(s), "l"(g));
}
__device__ __forceinline__ void cp_commit() {
    asm volatile("cp.async.commit_group;\n");
}
template<int N> __device__ __forceinline__ void cp_wait() {
    asm volatile("cp.async.wait_group %0;\n" :: "n"(N));
}

__device__ __forceinline__ void mma_tf32(float d[4], const float a[4], const float b[2]) {
    asm volatile(
        "mma.sync.aligned.m16n8k8.row.col.f32.tf32.tf32.f32 "
        "{%0,%1,%2,%3}, {%4,%5,%6,%7}, {%8,%9}, {%0,%1,%2,%3};\n"
        : "+f"(d[0]), "+f"(d[1]), "+f"(d[2]), "+f"(d[3])
        : "r"(__float_as_uint(a[0])), "r"(__float_as_uint(a[1])),
          "r"(__float_as_uint(a[2])), "r"(__float_as_uint(a[3])),
          "r"(__float_as_uint(b[0])), "r"(__float_as_uint(b[1])));
}

// ---------------------------------------------------------------------------
// One-time tf32 rounding pass (vectorized elementwise)
// ---------------------------------------------------------------------------
__global__ __launch_bounds__(256) void round_pass(
    const float* __restrict__ src, float* __restrict__ dst)
{
    const size_t i = ((size_t)blockIdx.x * 256 + threadIdx.x) * 4;
    float4 v = *(const float4*)(src + i);
    v.x = to_tf32(v.x); v.y = to_tf32(v.y);
    v.z = to_tf32(v.z); v.w = to_tf32(v.w);
    *(float4*)(dst + i) = v;
}

// ---------------------------------------------------------------------------
// tf32 tensor-core GEMM, cp.async double-buffered, pure-copy staging.
// C = A(M x 1024) @ Bw(1024 x N) + bias.  A,Bw pre-rounded to tf32.
// mode 0: QKV epilogue (scatter tf32-rounded to g_q/g_k/g_v)
// mode 1: proj epilogue (A is g_o — passed from host, write fp32 to out)
// Block 128x128, BK=16, 8 warps (2x4), warp tile 64x32.
// ---------------------------------------------------------------------------
#define APITCH 20    // A smem pitch: bank (20g+t4)%32 all-distinct
#define BPITCH 136   // B smem pitch: bank (8t4+g)%32 all-distinct

__global__ __launch_bounds__(256) void gemm_tf32(
    const float* __restrict__ A, const float* __restrict__ Bw,
    const float* __restrict__ bias, float* __restrict__ out,
    int N, int mode)
{
    __shared__ __align__(16) float As[2][128 * APITCH];  // [m][k]
    __shared__ __align__(16) float Bs[2][16 * BPITCH];   // [k][n]

    const int tid  = threadIdx.x;
    const int lane = tid & 31;
    const int wid  = tid >> 5;
    const int g    = lane >> 2;
    const int t4   = lane & 3;
    const int warp_m = (wid >> 2) * 64;
    const int warp_n = (wid & 3) * 32;
    const int m0 = blockIdx.y * 128;
    const int n0 = blockIdx.x * 128;

    float acc[4][4][4];
    #pragma unroll
    for (int i = 0; i < 4; i++)
        #pragma unroll
        for (int j = 0; j < 4; j++)
            #pragma unroll
            for (int r = 0; r < 4; r++) acc[i][j][r] = 0.f;

    // per-thread chunk map: A tile 128x16 = 512 x 16B chunks; B tile 16x128 = 512
    const int ach0 = tid * 2;
    const int bch0 = tid * 2;

    auto issue_tile = [&](int k0, int buf) {
        #pragma unroll
        for (int c = 0; c < 2; c++) {
            const int ch = ach0 + c;
            const int row = ch >> 2, col = (ch & 3) * 4;
            cp16(sptr(&As[buf][row * APITCH + col]),
                 A + (size_t)(m0 + row) * CC + k0 + col);
        }
        #pragma unroll
        for (int c = 0; c < 2; c++) {
            const int ch = bch0 + c;
            const int row = ch >> 5, col = (ch & 31) * 4;
            cp16(sptr(&Bs[buf][row * BPITCH + col]),
                 Bw + (size_t)(k0 + row) * N + n0 + col);
        }
        cp_commit();
    };

    issue_tile(0, 0);

    for (int k0 = 0; k0 < CC; k0 += 16) {
        const int buf = (k0 >> 4) & 1;
        const bool pf = (k0 + 16) < CC;
        if (pf) { issue_tile(k0 + 16, buf ^ 1); cp_wait<1>(); }
        else    { cp_wait<0>(); }
        __syncthreads();

        #pragma unroll
        for (int ks = 0; ks < 2; ks++) {
            const int kb = ks * 8;
            float af[4][4], bf[4][2];
            #pragma unroll
            for (int mt = 0; mt < 4; mt++) {
                const int m = warp_m + mt * 16 + g;
                af[mt][0] = As[buf][m * APITCH + kb + t4];
                af[mt][1] = As[buf][(m + 8) * APITCH + kb + t4];
                af[mt][2] = As[buf][m * APITCH + kb + t4 + 4];
                af[mt][3] = As[buf][(m + 8) * APITCH + kb + t4 + 4];
            }
            #pragma unroll
            for (int nt = 0; nt < 4; nt++) {
                const int n = warp_n + nt * 8 + g;
                bf[nt][0] = Bs[buf][(kb + t4) * BPITCH + n];
                bf[nt][1] = Bs[buf][(kb + t4 + 4) * BPITCH + n];
            }
            #pragma unroll
            for (int mt = 0; mt < 4; mt++)
                #pragma unroll
                for (int nt = 0; nt < 4; nt++)
                    mma_tf32(acc[mt][nt], af[mt], bf[nt]);
        }
        __syncthreads();   // reads of buf done before next iter overwrites it
    }

    #pragma unroll
    for (int mt = 0; mt < 4; mt++) {
        #pragma unroll
        for (int half = 0; half < 2; half++) {
            const int m = m0 + warp_m + mt * 16 + g + half * 8;
            #pragma unroll
            for (int nt = 0; nt < 4; nt++) {
                const int n = n0 + warp_n + nt * 8 + t4 * 2;
                float v0 = acc[mt][nt][half * 2 + 0] + bias[n];
                float v1 = acc[mt][nt][half * 2 + 1] + bias[n + 1];
                if (mode == 1) {
                    *(float2*)(out + (size_t)m * CC + n) = make_float2(v0, v1);
                } else {
                    const int s = n >> 10;            // 0:q 1:k 2:v
                    const int h = (n & 1023) >> 6;
                    const int d = n & 63;
                    const int bidx = m >> 11;
                    const int t = m & (TT - 1);
                    const size_t idx = (((size_t)(bidx * HH + h)) * TT + t) * DD + d;
                    const float QS = 0.125f * 1.44269504f;  // 1/sqrt(D) * log2(e)
                    if (s == 0)
                        *(float2*)(g_q + idx) = make_float2(to_tf32(v0 * QS), to_tf32(v1 * QS));
                    else if (s == 1)
                        *(float2*)(g_k + idx) = make_float2(to_tf32(v0), to_tf32(v1));
                    else
                        *(float2*)(g_v + idx) = make_float2(to_tf32(v0), to_tf32(v1));
                }
            }
        }
    }
}

// ---------------------------------------------------------------------------
// Tensor-core causal flash attention. CTA = 128 threads / 64-query tile.
// K/V pre-rounded tf32 in gmem -> pure cp.async staging (K double-buffered,
// V single-buffered hidden under S+softmax). P routed via per-warp smem.
// Dynamic smem: Ks[2][64*68] + Vs[64*72] + Ps[4][16*36] = 62464 B.
// ---------------------------------------------------------------------------
#define KPK 68   // Ks pitch: bank (4g+t4)%32 all-distinct for K b-frags
#define KPV 72   // Vs pitch: bank (8t4+g)%32 all-distinct for V b-frags
#define PP  36   // Ps pitch: bank (4g+t4)%32 all-distinct for a-frags
#define ATTN_SMEM ((2*64*KPK + 64*KPV + 4*16*PP) * 4)

__global__ __launch_bounds__(128, 3) void attn_tc()
{
    extern __shared__ __align__(16) float dsm[];
    float* Ks = dsm;                       // [2][64*KPK]
    float* Vs = dsm + 2 * 64 * KPK;        // [64*KPV]
    float* Ps = dsm + 2 * 64 * KPK + 64 * KPV;  // [4][16*PP]

    const int qt  = (int)gridDim.x - 1 - (int)blockIdx.x;  // heavy tiles first
    const int h   = blockIdx.y;
    const int b   = blockIdx.z;
    const int tid  = threadIdx.x;
    const int lane = tid & 31;
    const int w    = tid >> 5;
    const int g    = lane >> 2;
    const int t4   = lane & 3;

    const size_t head_off = ((size_t)(b * HH + h)) * TT * DD;
    const float* __restrict__ qb = g_q + head_off;
    const float* __restrict__ kb = g_k + head_off;
    const float* __restrict__ vb = g_v + head_off;

    // staging map: 2 threads per row, 32 floats (8 x 16B chunks) each
    const int srow = tid >> 1;
    const int scol = (tid & 1) * 32;

    auto issue_k = [&](int jt, int buf) {
        const float* src = kb + (size_t)(jt * 64 + srow) * DD + scol;
        uint32_t dst = sptr(&Ks[buf * 64 * KPK + srow * KPK + scol]);
        #pragma unroll
        for (int c = 0; c < 32; c += 4) cp16(dst + c * 4, src + c);
    };
    auto issue_v = [&](int jt) {
        const float* src = vb + (size_t)(jt * 64 + srow) * DD + scol;
        uint32_t dst = sptr(&Vs[srow * KPV + scol]);
        #pragma unroll
        for (int c = 0; c < 32; c += 4) cp16(dst + c * 4, src + c);
    };

    // Q fragments in registers (pre-rounded + pre-scaled in gmem)
    float qf[8][4];
    {
        const int r0 = qt * 64 + w * 16 + g;
        #pragma unroll
        for (int kc = 0; kc < 8; kc++) {
            qf[kc][0] = qb[(size_t)r0 * DD + kc * 8 + t4];
            qf[kc][1] = qb[(size_t)(r0 + 8) * DD + kc * 8 + t4];
            qf[kc][2] = qb[(size_t)r0 * DD + kc * 8 + t4 + 4];
            qf[kc][3] = qb[(size_t)(r0 + 8) * DD + kc * 8 + t4 + 4];
        }
    }

    float o[8][4];
    #pragma unroll
    for (int nt = 0; nt < 8; nt++)
        #pragma unroll
        for (int r = 0; r < 4; r++) o[nt][r] = 0.f;
    float m0 = -1e30f, m1 = -1e30f, l0 = 0.f, l1 = 0.f;

    float* pb = Ps + w * 16 * PP;

    issue_k(0, 0);
    cp_commit();

    for (int jt = 0; jt <= qt; jt++) {
        const int buf = jt & 1;

        __syncthreads();                 // Vs free (prev PV done)
        issue_v(jt);
        if (jt < qt) issue_k(jt + 1, buf ^ 1);
        cp_commit();

        cp_wait<1>();                    // K[jt] complete
        __syncthreads();

        // ---- S = Q @ K^T  (warp strip 16 x 64) ----
        float s[8][4];
        #pragma unroll
        for (int nt = 0; nt < 8; nt++)
            #pragma unroll
            for (int r = 0; r < 4; r++) s[nt][r] = 0.f;

        const float* kbuf = Ks + buf * 64 * KPK;
        #pragma unroll
        for (int kc = 0; kc < 8; kc++) {
            #pragma unroll
            for (int nt = 0; nt < 8; nt++) {
                float bk[2];
                bk[0] = kbuf[(nt * 8 + g) * KPK + kc * 8 + t4];
                bk[1] = kbuf[(nt * 8 + g) * KPK + kc * 8 + t4 + 4];
                mma_tf32(s[nt], qf[kc], bk);
            }
        }

        // ---- causal mask on diagonal tile ----
        if (jt == qt) {
            const int rlo = w * 16 + g;
            const int rhi = rlo + 8;
            #pragma unroll
            for (int nt = 0; nt < 8; nt++) {
                const int col = nt * 8 + 2 * t4;
                if (col     > rlo) s[nt][0] = -1e30f;
                if (col + 1 > rlo) s[nt][1] = -1e30f;
                if (col     > rhi) s[nt][2] = -1e30f;
                if (col + 1 > rhi) s[nt][3] = -1e30f;
            }
        }

        // ---- online softmax (2^ domain; log2e folded into q) ----
        float mx0 = -1e30f, mx1 = -1e30f;
        #pragma unroll
        for (int nt = 0; nt < 8; nt++) {
            mx0 = fmaxf(mx0, fmaxf(s[nt][0], s[nt][1]));
            mx1 = fmaxf(mx1, fmaxf(s[nt][2], s[nt][3]));
        }
        mx0 = fmaxf(mx0, __shfl_xor_sync(0xffffffffu, mx0, 1));
        mx0 = fmaxf(mx0, __shfl_xor_sync(0xffffffffu, mx0, 2));
        mx1 = fmaxf(mx1, __shfl_xor_sync(0xffffffffu, mx1, 1));
        mx1 = fmaxf(mx1, __shfl_xor_sync(0xffffffffu, mx1, 2));

        const float mn0 = fmaxf(m0, mx0);
        const float mn1 = fmaxf(m1, mx1);
        const float c0 = ex2(m0 - mn0);
        const float c1 = ex2(m1 - mn1);
        m0 = mn0; m1 = mn1;
        l0 *= c0; l1 *= c1;
        #pragma unroll
        for (int nt = 0; nt < 8; nt++) {
            o[nt][0] *= c0; o[nt][1] *= c0;
            o[nt][2] *= c1; o[nt][3] *= c1;
        }

        float r0 = 0.f, r1 = 0.f;
        #pragma unroll
        for (int nt = 0; nt < 8; nt++) {
            s[nt][0] = ex2(s[nt][0] - mn0);
            s[nt][1] = ex2(s[nt][1] - mn0);
            s[nt][2] = ex2(s[nt][2] - mn1);
            s[nt][3] = ex2(s[nt][3] - mn1);
            r0 += s[nt][0] + s[nt][1];
            r1 += s[nt][2] + s[nt][3];
        }
        r0 += __shfl_xor_sync(0xffffffffu, r0, 1);
        r0 += __shfl_xor_sync(0xffffffffu, r0, 2);
        r1 += __shfl_xor_sync(0xffffffffu, r1, 1);
        r1 += __shfl_xor_sync(0xffffffffu, r1, 2);
        l0 += r0; l1 += r1;

        cp_wait<0>();                    // V[jt] (and K[jt+1]) complete
        __syncthreads();

        // ---- O += P @ V  via per-warp smem P buffer, 32 keys per half ----
        #pragma unroll
        for (int half = 0; half < 2; half++) {
            #pragma unroll
            for (int q = 0; q < 4; q++) {
                const int nt = half * 4 + q;
                const int col = q * 8 + 2 * t4;
                *(float2*)&pb[g * PP + col] =
                    make_float2(to_tf32(s[nt][0]), to_tf32(s[nt][1]));
                *(float2*)&pb[(g + 8) * PP + col] =
                    make_float2(to_tf32(s[nt][2]), to_tf32(s[nt][3]));
            }
            __syncwarp();
            #pragma unroll
            for (int kc2 = 0; kc2 < 4; kc2++) {
                const int kc = half * 4 + kc2;
                float a[4];
                a[0] = pb[g * PP + kc2 * 8 + t4];
                a[1] = pb[(g + 8) * PP + kc2 * 8 + t4];
                a[2] = pb[g * PP + kc2 * 8 + t4 + 4];
                a[3] = pb[(g + 8) * PP + kc2 * 8 + t4 + 4];
                #pragma unroll
                for (int nt = 0; nt < 8; nt++) {
                    float bv[2];
                    bv[0] = Vs[(kc * 8 + t4) * KPV + nt * 8 + g];
                    bv[1] = Vs[(kc * 8 + t4 + 4) * KPV + nt * 8 + g];
                    mma_tf32(o[nt], a, bv);
                }
            }
            __syncwarp();
        }
    }

    // ---- epilogue: normalize + store tf32-rounded to g_o ----
    const float i0 = 1.f / l0;
    const float i1 = 1.f / l1;
    const int qrow = qt * 64 + w * 16;
    float* ob = g_o + ((size_t)(b * TT) + qrow) * CC + h * DD;
    #pragma unroll
    for (int nt = 0; nt < 8; nt++) {
        const int d = nt * 8 + 2 * t4;
        *(float2*)(ob + (size_t)g * CC + d) =
            make_float2(to_tf32(o[nt][0] * i0), to_tf32(o[nt][1] * i0));
        *(float2*)(ob + (size_t)(g + 8) * CC + d) =
            make_float2(to_tf32(o[nt][2] * i1), to_tf32(o[nt][3] * i1));
    }
}

extern "C" void kernel_launch(void* const* d_in, const int* in_sizes, int n_in,
                              void* d_out, int out_size)
{
    const float* x      = (const float*)d_in[0];
    const float* w_qkv  = (const float*)d_in[1];
    const float* b_qkv  = (const float*)d_in[2];
    const float* w_proj = (const float*)d_in[3];
    const float* b_proj = (const float*)d_in[4];
    float* out = (float*)d_out;

    float *d_xr, *d_wq, *d_wp, *d_o;
    cudaGetSymbolAddress((void**)&d_xr, g_xr);
    cudaGetSymbolAddress((void**)&d_wq, g_wq);
    cudaGetSymbolAddress((void**)&d_wp, g_wp);
    cudaGetSymbolAddress((void**)&d_o,  g_o);

    cudaFuncSetAttribute(attn_tc, cudaFuncAttributeMaxDynamicSharedMemorySize,
                         ATTN_SMEM);

    // one-time tf32 pre-rounding (elementwise, ~100MB traffic)
    round_pass<<<(MROWS * CC) / 1024, 256>>>(x, d_xr);
    round_pass<<<(CC * NQKV) / 1024, 256>>>(w_qkv, d_wq);
    round_pass<<<(CC * CC) / 1024, 256>>>(w_proj, d_wp);

    dim3 g1(NQKV / 128, MROWS / 128);   // (24, 64)
    gemm_tf32<<<g1, 256>>>(d_xr, d_wq, b_qkv, nullptr, NQKV, 0);

    dim3 g2(TT / 64, HH, BB);           // (32, 16, 4)
    attn_tc<<<g2, 128, ATTN_SMEM>>>();

    dim3 g3(CC / 128, MROWS / 128);     // (8, 64)
    gemm_tf32<<<g3, 256>>>(d_o, d_wp, b_proj, out, CC, 1);
}